// round 2
// baseline (speedup 1.0000x reference)
#include <cuda_runtime.h>

// ArcFace loss:
//   tgt[i]   = wf[i, labels[i]]
//   num[i]   = S * cos(acos(clip(tgt)) + M)  ==  S*(t*cosM - sqrt(1-t^2)*sinM)
//   excl[i]  = sum_j exp(S*wf[i,j]) - exp(S*tgt[i])
//   L[i]     = num[i] - log(exp(num[i]) + excl[i])
//   out      = -mean(L)
//
// wf: [B=8192, C=10000] fp32 (327.7 MB -> HBM-bound single pass)
// labels: [B], interpreted as int32 (harness downcasts int64 indices)

#define MAX_B 16384

static __device__ float g_L[MAX_B];

#define SCALE 64.0f
#define COS_M 0.8775825618903728f   // cos(0.5)
#define SIN_M 0.479425538604203f    // sin(0.5)
#define EPSC  1e-7f

__global__ __launch_bounds__(256) void arcface_row_kernel(
    const float* __restrict__ wf,
    const int* __restrict__ labels,
    int C)
{
    const int row = blockIdx.x;
    const float* __restrict__ p = wf + (size_t)row * (size_t)C;

    float acc = 0.0f;

    // Vectorized main path (C % 4 == 0: 10000 = 2500 * 4)
    const int n4 = C >> 2;
    const float4* __restrict__ p4 = (const float4*)p;
    for (int i = threadIdx.x; i < n4; i += 256) {
        float4 v = p4[i];
        acc += __expf(SCALE * v.x);
        acc += __expf(SCALE * v.y);
        acc += __expf(SCALE * v.z);
        acc += __expf(SCALE * v.w);
    }
    // Scalar tail (empty when C % 4 == 0)
    for (int i = (n4 << 2) + threadIdx.x; i < C; i += 256) {
        acc += __expf(SCALE * p[i]);
    }

    // Block reduction: warp shuffle then smem across 8 warps
    #pragma unroll
    for (int o = 16; o > 0; o >>= 1)
        acc += __shfl_down_sync(0xffffffffu, acc, o);

    __shared__ float warp_sums[8];
    const int lane = threadIdx.x & 31;
    const int wid  = threadIdx.x >> 5;
    if (lane == 0) warp_sums[wid] = acc;
    __syncthreads();

    if (threadIdx.x == 0) {
        float s = 0.0f;
        #pragma unroll
        for (int i = 0; i < 8; i++) s += warp_sums[i];

        // Labels as int32 (harness convention). Clamp defensively so a dtype
        // mismatch shows up as a numeric error, never an illegal access.
        int lbl = labels[row];
        lbl = max(0, min(lbl, C - 1));

        const float t = p[lbl];                          // target cosine (L2-hot)
        float tc = fminf(fmaxf(t, -1.0f + EPSC), 1.0f - EPSC);
        float num = SCALE * (tc * COS_M - sqrtf(fmaxf(1.0f - tc * tc, 0.0f)) * SIN_M);
        float excl = s - __expf(SCALE * t);
        float denom = __expf(num) + excl;
        g_L[row] = num - __logf(denom);
    }
}

__global__ __launch_bounds__(1024) void arcface_reduce_kernel(float* __restrict__ out, int B)
{
    __shared__ float sdata[1024];
    float acc = 0.0f;
    for (int i = threadIdx.x; i < B; i += 1024)
        acc += g_L[i];
    sdata[threadIdx.x] = acc;
    __syncthreads();
    #pragma unroll
    for (int s = 512; s > 0; s >>= 1) {
        if (threadIdx.x < s) sdata[threadIdx.x] += sdata[threadIdx.x + s];
        __syncthreads();
    }
    if (threadIdx.x == 0)
        out[0] = -sdata[0] / (float)B;
}

extern "C" void kernel_launch(void* const* d_in, const int* in_sizes, int n_in,
                              void* d_out, int out_size)
{
    const float* wf     = (const float*)d_in[0];
    const int*   labels = (const int*)d_in[1];
    float*       out    = (float*)d_out;

    const int B = in_sizes[1];               // 8192
    const int C = in_sizes[0] / B;           // 10000

    arcface_row_kernel<<<B, 256>>>(wf, labels, C);
    arcface_reduce_kernel<<<1, 1024>>>(out, B);
}